// round 7
// baseline (speedup 1.0000x reference)
#include <cuda_runtime.h>
#include <cuda_bf16.h>
#include <cstdint>

#define BB 512
#define DD 256
#define PP 196
#define P0 8          // positions computed exactly; p>=P0 uses analytic uniform-G path
#define SPITCH 264    // padded bf16 row pitch (528B) -> conflict-free ldmatrix
#define NUNITS 848    // 784 (A: 196p x 4 strips) + 32 (B, p<8) + 32 (C, p<8)

// ---------------- scratch (static device arrays; no allocation) ----------------
__device__ __nv_bfloat16 g_hat[(size_t)P0 * BB * DD];   // normalized softmax^p(g), p<P0
__device__ __nv_bfloat16 lf_hat[(size_t)PP * BB * DD];  // normalized softmax(local)
__device__ float d_pos[(size_t)PP * BB];                // sim of the positive pair
__device__ float rowA_g[(size_t)PP * BB];
__device__ float rowB_g[(size_t)P0 * BB];
__device__ float rowC_g[(size_t)P0 * BB];
__device__ float colB_g[(size_t)P0 * BB];
__device__ float w_g[PP];
__device__ float part_g[PP];

// ---------------- helpers ----------------
__device__ __forceinline__ uint32_t smem_u32(const void* p) {
    return (uint32_t)__cvta_generic_to_shared(p);
}
__device__ __forceinline__ void ldsm_x4(uint32_t& r0, uint32_t& r1, uint32_t& r2,
                                        uint32_t& r3, uint32_t addr) {
    asm volatile("ldmatrix.sync.aligned.m8n8.x4.shared.b16 {%0,%1,%2,%3}, [%4];\n"
                 : "=r"(r0), "=r"(r1), "=r"(r2), "=r"(r3)
                 : "r"(addr));
}
__device__ __forceinline__ void mma16816(float* c, const uint32_t* a, const uint32_t* b) {
    asm volatile(
        "mma.sync.aligned.m16n8k16.row.col.f32.bf16.bf16.f32 "
        "{%0,%1,%2,%3}, {%4,%5,%6,%7}, {%8,%9}, {%0,%1,%2,%3};\n"
        : "+f"(c[0]), "+f"(c[1]), "+f"(c[2]), "+f"(c[3])
        : "r"(a[0]), "r"(a[1]), "r"(a[2]), "r"(a[3]), "r"(b[0]), "r"(b[1]));
}
__device__ __forceinline__ void cp16(uint32_t dst, const void* src) {
    asm volatile("cp.async.cg.shared.global [%0], [%1], 16;\n" ::"r"(dst), "l"(src));
}
#define CP_COMMIT() asm volatile("cp.async.commit_group;\n" ::: "memory")
#define CP_WAIT0() asm volatile("cp.async.wait_group 0;\n" ::: "memory")
#define CP_WAIT1() asm volatile("cp.async.wait_group 1;\n" ::: "memory")

__device__ __forceinline__ void load_strip(uint32_t sb, const __nv_bfloat16* src,
                                           int tid) {
    // 128 rows x 256 bf16 -> smem rows of pitch SPITCH, 16B chunks
    for (int i = tid; i < 128 * 32; i += 256) {
        int r = i >> 5, cs = i & 31;
        cp16(sb + (uint32_t)(r * SPITCH * 2 + cs * 16), src + (size_t)r * DD + cs * 8);
    }
}

__device__ __forceinline__ void unit_decode(int u, int& mat, int& p, int& s) {
    if (u < 784) { mat = 0; p = u >> 2; s = u & 3; }
    else if (u < 816) { int v = u - 784; mat = 1; p = v >> 2; s = v & 3; }
    else { int v = u - 816; mat = 2; p = v >> 2; s = v & 3; }
}

// ---------------- kernel 1: repeated-softmax chain (P0 steps) ----------------
__global__ void g_chain_kernel(const float* __restrict__ g0) {
    int warp = threadIdx.x >> 5, lane = threadIdx.x & 31;
    int b = blockIdx.x * 8 + warp;
    float v[8];
#pragma unroll
    for (int r = 0; r < 8; r++) v[r] = g0[b * DD + r * 32 + lane];
    for (int p = 0; p < P0; p++) {
        float m = v[0];
#pragma unroll
        for (int r = 1; r < 8; r++) m = fmaxf(m, v[r]);
#pragma unroll
        for (int s = 16; s > 0; s >>= 1) m = fmaxf(m, __shfl_xor_sync(0xffffffffu, m, s));
        float s = 0.f;
#pragma unroll
        for (int r = 0; r < 8; r++) { v[r] = __expf(v[r] - m); s += v[r]; }
#pragma unroll
        for (int t = 16; t > 0; t >>= 1) s += __shfl_xor_sync(0xffffffffu, s, t);
        float inv = 1.f / s;
        float sq = 0.f;
#pragma unroll
        for (int r = 0; r < 8; r++) { v[r] *= inv; sq += v[r] * v[r]; }
#pragma unroll
        for (int t = 16; t > 0; t >>= 1) sq += __shfl_xor_sync(0xffffffffu, sq, t);
        float sc = 1.f / (sqrtf(sq) + 1e-8f);
        __nv_bfloat16* dst = &g_hat[((size_t)p * BB + b) * DD];
#pragma unroll
        for (int r = 0; r < 8; r++) dst[r * 32 + lane] = __float2bfloat16(v[r] * sc);
    }
}

// ---------------- kernel 2: fused gather + softmax + normalize + positive dot ----
// one block per b; stage outputs[b] (256x196 f32) in smem pitch 197 (conflict-free)
__global__ void __launch_bounds__(512, 1) lf_fused_kernel(const float* __restrict__ outp) {
    extern __shared__ float fs[];  // 256 * 197 floats
    int b = blockIdx.x, tid = threadIdx.x, lane = tid & 31, warp = tid >> 5;
    const float* src = outp + (size_t)b * DD * PP;
    for (int d = warp; d < DD; d += 16)
        for (int q = lane; q < PP; q += 32) fs[d * 197 + q] = src[d * PP + q];
    __syncthreads();
    for (int p = warp; p < PP; p += 16) {
        float v[8];
#pragma unroll
        for (int r = 0; r < 8; r++) v[r] = fs[(r * 32 + lane) * 197 + p];
        float m = v[0];
#pragma unroll
        for (int r = 1; r < 8; r++) m = fmaxf(m, v[r]);
#pragma unroll
        for (int s = 16; s > 0; s >>= 1) m = fmaxf(m, __shfl_xor_sync(0xffffffffu, m, s));
        float s = 0.f;
#pragma unroll
        for (int r = 0; r < 8; r++) { v[r] = __expf(v[r] - m); s += v[r]; }
#pragma unroll
        for (int t = 16; t > 0; t >>= 1) s += __shfl_xor_sync(0xffffffffu, s, t);
        float inv = 1.f / s;
        float sq = 0.f;
#pragma unroll
        for (int r = 0; r < 8; r++) { v[r] *= inv; sq += v[r] * v[r]; }
#pragma unroll
        for (int t = 16; t > 0; t >>= 1) sq += __shfl_xor_sync(0xffffffffu, sq, t);
        float sc = 1.f / (sqrtf(sq) + 1e-8f);
        __nv_bfloat16* dst = &lf_hat[((size_t)p * BB + b) * DD];
        float dot = 0.f;
        if (p < P0) {
            const __nv_bfloat16* gp = &g_hat[((size_t)p * BB + b) * DD];
#pragma unroll
            for (int r = 0; r < 8; r++) {
                float z = v[r] * sc;
                dst[r * 32 + lane] = __float2bfloat16(z);
                dot += z * __bfloat162float(gp[r * 32 + lane]);
            }
#pragma unroll
            for (int t = 16; t > 0; t >>= 1) dot += __shfl_xor_sync(0xffffffffu, dot, t);
        } else {
            float ssum = 0.f;
#pragma unroll
            for (int r = 0; r < 8; r++) {
                float z = v[r] * sc;
                dst[r * 32 + lane] = __float2bfloat16(z);
                ssum += z;
            }
#pragma unroll
            for (int t = 16; t > 0; t >>= 1) ssum += __shfl_xor_sync(0xffffffffu, ssum, t);
            dot = ssum * (1.f / 16.f);  // X_i . uniform-unit-G
        }
        if (lane == 0) d_pos[(size_t)p * BB + b] = 2.f * dot;
    }
}

// ---------------- kernel 3: attention sums (fully coalesced column-sum) --------
__global__ void wsum_kernel(const float* __restrict__ att) {
    int tid = threadIdx.x;
    int r0 = blockIdx.x * 32;  // 128 blocks x 32 rows covers 4096 rows
    float acc = 0.f;
    if (tid < PP) {
#pragma unroll 4
        for (int r = 0; r < 32; r++) acc += att[(size_t)(r0 + r) * PP + tid];
        atomicAdd(&w_g[tid], acc);
    }
}

// ---------------- kernel 4: persistent mma.sync Gram GEMM + exp row/col sums ----
// 148 persistent blocks, 256 threads (8 warps, 2x4). Unit = (mat, p, s): A strip
// kept in smem across 1-4 B chunks; B double-buffered via cp.async groups.
__global__ void __launch_bounds__(256, 1) gemm_kernel() {
    extern __shared__ __align__(16) __nv_bfloat16 smem[];
    uint32_t sA_u = smem_u32(smem);
    uint32_t sB_u[2] = {sA_u + 128 * SPITCH * 2, sA_u + 2 * 128 * SPITCH * 2};

    int tid = threadIdx.x, lane = tid & 31, warp = tid >> 5;
    int warpM = warp & 1, warpN = warp >> 1;
    int g8 = lane & 7, q = lane >> 3;
    int g4 = lane >> 2, c2 = (lane & 3) * 2;

    for (int u = blockIdx.x; u < NUNITS; u += gridDim.x) {
        int mat, p, s;
        unit_decode(u, mat, p, s);
        int cstart = (mat == 1) ? 0 : s;
        const __nv_bfloat16* L = (mat == 2) ? g_hat : lf_hat;
        const __nv_bfloat16* R = (mat == 0) ? lf_hat : g_hat;

        load_strip(sA_u, L + ((size_t)p * BB + s * 128) * DD, tid);
        load_strip(sB_u[0], R + ((size_t)p * BB + cstart * 128) * DD, tid);
        CP_COMMIT();

        float rowpart[8];
#pragma unroll
        for (int k = 0; k < 8; k++) rowpart[k] = 0.f;

        int nb = 0;
        for (int c = cstart; c < 4; c++) {
            // prefetch next chunk into the other buffer (safe: its last readers
            // passed the trailing __syncthreads of iteration c-1)
            if (c + 1 < 4) {
                load_strip(sB_u[nb ^ 1], R + ((size_t)p * BB + (c + 1) * 128) * DD, tid);
                CP_COMMIT();
                CP_WAIT1();
            } else {
                CP_WAIT0();
            }
            __syncthreads();

            float acc[4][4][4];
#pragma unroll
            for (int mt = 0; mt < 4; mt++)
#pragma unroll
                for (int nt = 0; nt < 4; nt++)
#pragma unroll
                    for (int e = 0; e < 4; e++) acc[mt][nt][e] = 0.f;

            uint32_t sBc = sB_u[nb];
            for (int kk = 0; kk < DD; kk += 16) {
                uint32_t a[4][4], bfr[4][2];
#pragma unroll
                for (int mt = 0; mt < 4; mt++) {
                    int ar = warpM * 64 + mt * 16 + g8 + ((q & 1) ? 8 : 0);
                    int ac = kk + ((q & 2) ? 8 : 0);
                    ldsm_x4(a[mt][0], a[mt][1], a[mt][2], a[mt][3],
                            sA_u + (uint32_t)(ar * SPITCH + ac) * 2u);
                }
#pragma unroll
                for (int pr = 0; pr < 2; pr++) {
                    int nbv = warpN * 32 + pr * 16 + ((q & 2) ? 8 : 0) + g8;
                    int bc = kk + ((q & 1) ? 8 : 0);
                    ldsm_x4(bfr[2 * pr][0], bfr[2 * pr][1], bfr[2 * pr + 1][0],
                            bfr[2 * pr + 1][1], sBc + (uint32_t)(nbv * SPITCH + bc) * 2u);
                }
#pragma unroll
                for (int mt = 0; mt < 4; mt++)
#pragma unroll
                    for (int nt = 0; nt < 4; nt++) mma16816(acc[mt][nt], a[mt], bfr[nt]);
            }

            // epilogue: e = exp(2*dot), diag exclusion on diag blocks of A/C
            bool excl = (mat != 1) && (c == s);
            bool docol = (mat == 1) || (c > s);
            float cp[8];
#pragma unroll
            for (int k = 0; k < 8; k++) cp[k] = 0.f;
#pragma unroll
            for (int mt = 0; mt < 4; mt++) {
                int row_lo = warpM * 64 + mt * 16 + g4;
#pragma unroll
                for (int nt = 0; nt < 4; nt++) {
                    int col = warpN * 32 + nt * 8 + c2;
                    float e0 = __expf(2.f * acc[mt][nt][0]);
                    float e1 = __expf(2.f * acc[mt][nt][1]);
                    float e2 = __expf(2.f * acc[mt][nt][2]);
                    float e3 = __expf(2.f * acc[mt][nt][3]);
                    if (excl) {
                        if (row_lo == col) e0 = 0.f;
                        if (row_lo == col + 1) e1 = 0.f;
                        if (row_lo + 8 == col) e2 = 0.f;
                        if (row_lo + 8 == col + 1) e3 = 0.f;
                    }
                    rowpart[2 * mt] += e0 + e1;
                    rowpart[2 * mt + 1] += e2 + e3;
                    if (docol) {
                        cp[2 * nt] += e0 + e2;
                        cp[2 * nt + 1] += e1 + e3;
                    }
                }
            }
            if (docol) {
#pragma unroll
                for (int k = 0; k < 8; k++) {
                    cp[k] += __shfl_xor_sync(0xffffffffu, cp[k], 4);
                    cp[k] += __shfl_xor_sync(0xffffffffu, cp[k], 8);
                    cp[k] += __shfl_xor_sync(0xffffffffu, cp[k], 16);
                }
                float* cdst = (mat == 1) ? colB_g : ((mat == 0) ? rowA_g : rowC_g);
                if (lane < 4) {
#pragma unroll
                    for (int nt = 0; nt < 4; nt++) {
                        int col = c * 128 + warpN * 32 + nt * 8 + lane * 2;
                        atomicAdd(&cdst[(size_t)p * BB + col], cp[2 * nt]);
                        atomicAdd(&cdst[(size_t)p * BB + col + 1], cp[2 * nt + 1]);
                    }
                }
            }
            __syncthreads();  // all warps done with sB_u[nb] before it is refilled
            nb ^= 1;
        }

        // flush row sums for this unit
#pragma unroll
        for (int k = 0; k < 8; k++) {
            rowpart[k] += __shfl_xor_sync(0xffffffffu, rowpart[k], 1);
            rowpart[k] += __shfl_xor_sync(0xffffffffu, rowpart[k], 2);
        }
        float* rdst = (mat == 0) ? rowA_g : ((mat == 1) ? rowB_g : rowC_g);
        if ((lane & 3) == 0) {
#pragma unroll
            for (int mt = 0; mt < 4; mt++) {
                int row = s * 128 + warpM * 64 + mt * 16 + g4;
                atomicAdd(&rdst[(size_t)p * BB + row], rowpart[2 * mt]);
                atomicAdd(&rdst[(size_t)p * BB + row + 8], rowpart[2 * mt + 1]);
            }
        }
    }
}

// ---------------- kernel 5: per-position loss ----------------
__global__ void finalize1_kernel() {
    __shared__ float red[16];
    __shared__ float Tsh;
    int p = blockIdx.x, tid = threadIdx.x;
    int lane = tid & 31, warp = tid >> 5;
    size_t base = (size_t)p * BB + tid;
    float dp = d_pos[base];
    float rA = rowA_g[base];
    float stop, sbot;
    if (p < P0) {
        stop = rA + rowB_g[base];
        sbot = rowC_g[base] + colB_g[base];
    } else {
        float e = __expf(dp);
        float t = e;
#pragma unroll
        for (int s = 16; s > 0; s >>= 1) t += __shfl_xor_sync(0xffffffffu, t, s);
        if (lane == 0) red[warp] = t;
        __syncthreads();
        if (warp == 0) {
            t = red[lane & 15];
#pragma unroll
            for (int s = 8; s > 0; s >>= 1) t += __shfl_xor_sync(0xffffffffu, t, s);
            if (lane == 0) Tsh = t;
        }
        __syncthreads();
        stop = rA + 512.f * e;
        sbot = Tsh + 511.f * 7.3890560989306495f;  // 511*e^2
        __syncthreads();
    }
    float v = 2.f * dp - logf(stop) - logf(sbot);
#pragma unroll
    for (int s = 16; s > 0; s >>= 1) v += __shfl_xor_sync(0xffffffffu, v, s);
    if (lane == 0) red[warp] = v;
    __syncthreads();
    if (warp == 0) {
        v = red[lane & 15];
#pragma unroll
        for (int s = 8; s > 0; s >>= 1) v += __shfl_xor_sync(0xffffffffu, v, s);
        if (lane == 0)
            part_g[p] = -w_g[p] * (1.f / (512.f * 196.f)) * v * (1.f / 1024.f);
    }
}

// ---------------- kernel 6: final sum ----------------
__global__ void finalize2_kernel(float* __restrict__ out) {
    __shared__ float red[8];
    int tid = threadIdx.x;
    float v = (tid < PP) ? part_g[tid] : 0.f;
    int lane = tid & 31, warp = tid >> 5;
#pragma unroll
    for (int s = 16; s > 0; s >>= 1) v += __shfl_xor_sync(0xffffffffu, v, s);
    if (lane == 0) red[warp] = v;
    __syncthreads();
    if (warp == 0) {
        v = (lane < 8) ? red[lane] : 0.f;
#pragma unroll
        for (int s = 4; s > 0; s >>= 1) v += __shfl_xor_sync(0xffffffffu, v, s);
        if (lane == 0) out[0] = v;
    }
}

// ---------------- launch ----------------
extern "C" void kernel_launch(void* const* d_in, const int* in_sizes, int n_in,
                              void* d_out, int out_size) {
    const float* gf = (const float*)d_in[0];    // global_feature [512,256]
    const float* att = (const float*)d_in[1];   // att [512,8,14,14]
    const float* outp = (const float*)d_in[2];  // outputs [512,256,14,14]
    float* out = (float*)d_out;

    const int gemm_smem = 3 * 128 * SPITCH * 2;  // A + 2xB = 198 KB
    const int lf_smem = DD * 197 * 4;            // ~197 KB
    cudaFuncSetAttribute(gemm_kernel, cudaFuncAttributeMaxDynamicSharedMemorySize,
                         gemm_smem);
    cudaFuncSetAttribute(lf_fused_kernel, cudaFuncAttributeMaxDynamicSharedMemorySize,
                         lf_smem);

    void *pA, *pB, *pC, *pCol, *pW;
    cudaGetSymbolAddress(&pA, rowA_g);
    cudaGetSymbolAddress(&pB, rowB_g);
    cudaGetSymbolAddress(&pC, rowC_g);
    cudaGetSymbolAddress(&pCol, colB_g);
    cudaGetSymbolAddress(&pW, w_g);
    cudaMemsetAsync(pA, 0, (size_t)PP * BB * sizeof(float));
    cudaMemsetAsync(pB, 0, (size_t)P0 * BB * sizeof(float));
    cudaMemsetAsync(pC, 0, (size_t)P0 * BB * sizeof(float));
    cudaMemsetAsync(pCol, 0, (size_t)P0 * BB * sizeof(float));
    cudaMemsetAsync(pW, 0, PP * sizeof(float));

    g_chain_kernel<<<64, 256>>>(gf);
    lf_fused_kernel<<<BB, 512, lf_smem>>>(outp);
    wsum_kernel<<<128, 256>>>(att);  // 4096 rows = 128 blocks x 32 rows
    gemm_kernel<<<148, 256, gemm_smem>>>();
    finalize1_kernel<<<PP, 512>>>();
    finalize2_kernel<<<1, 256>>>(out);
}

// round 15
// speedup vs baseline: 2.4056x; 2.4056x over previous
#include <cuda_runtime.h>
#include <cuda_bf16.h>
#include <cstdint>

#define BB 512
#define DD 256
#define PP 196
#define P0 8          // positions computed exactly; p>=P0 uses analytic uniform-G path
#define SPITCH 264    // padded bf16 row pitch (528B) -> conflict-free ldmatrix
#define NUNITS 848    // 784 (A) + 32 (B, p<8) + 32 (C, p<8)
#define PT 28         // p-tile for lf prep (196 = 7*28)
#define LPITCH 29     // f32 smem pitch; 29 odd -> conflict-free strided reads

// ---------------- scratch (static device arrays; no allocation) ----------------
__device__ __nv_bfloat16 g_hat[(size_t)P0 * BB * DD];   // normalized softmax^p(g), p<P0
__device__ __nv_bfloat16 lf_hat[(size_t)PP * BB * DD];  // normalized softmax(local)
__device__ float d_pos[(size_t)PP * BB];                // sim of the positive pair
__device__ float rowA_g[(size_t)PP * BB];
__device__ float rowB_g[(size_t)P0 * BB];
__device__ float rowC_g[(size_t)P0 * BB];
__device__ float colB_g[(size_t)P0 * BB];
__device__ float w_g[PP];
__device__ float part_g[PP];
__device__ unsigned int unit_ctr;

// ---------------- helpers ----------------
__device__ __forceinline__ uint32_t smem_u32(const void* p) {
    return (uint32_t)__cvta_generic_to_shared(p);
}
__device__ __forceinline__ void ldsm_x4(uint32_t& r0, uint32_t& r1, uint32_t& r2,
                                        uint32_t& r3, uint32_t addr) {
    asm volatile("ldmatrix.sync.aligned.m8n8.x4.shared.b16 {%0,%1,%2,%3}, [%4];\n"
                 : "=r"(r0), "=r"(r1), "=r"(r2), "=r"(r3)
                 : "r"(addr));
}
__device__ __forceinline__ void mma16816(float* c, const uint32_t* a, const uint32_t* b) {
    asm volatile(
        "mma.sync.aligned.m16n8k16.row.col.f32.bf16.bf16.f32 "
        "{%0,%1,%2,%3}, {%4,%5,%6,%7}, {%8,%9}, {%0,%1,%2,%3};\n"
        : "+f"(c[0]), "+f"(c[1]), "+f"(c[2]), "+f"(c[3])
        : "r"(a[0]), "r"(a[1]), "r"(a[2]), "r"(a[3]), "r"(b[0]), "r"(b[1]));
}
__device__ __forceinline__ void cp16(uint32_t dst, const void* src) {
    asm volatile("cp.async.cg.shared.global [%0], [%1], 16;\n" ::"r"(dst), "l"(src));
}
#define CP_COMMIT() asm volatile("cp.async.commit_group;\n" ::: "memory")
#define CP_WAIT0() asm volatile("cp.async.wait_group 0;\n" ::: "memory")
#define CP_WAIT1() asm volatile("cp.async.wait_group 1;\n" ::: "memory")

__device__ __forceinline__ void load_strip(uint32_t sb, const __nv_bfloat16* src,
                                           int tid) {
    for (int i = tid; i < 128 * 32; i += 256) {
        int r = i >> 5, cs = i & 31;
        cp16(sb + (uint32_t)(r * SPITCH * 2 + cs * 16), src + (size_t)r * DD + cs * 8);
    }
}

// LPT order: cost-4 units first (A s=0, B, C s=0), then descending.
__device__ __forceinline__ void unit_decode(int u, int& mat, int& p, int& s) {
    if (u < 196) { mat = 0; s = 0; p = u; }
    else if (u < 204) { mat = 2; s = 0; p = u - 196; }
    else if (u < 236) { int v = u - 204; mat = 1; s = v & 3; p = v >> 2; }
    else if (u < 432) { mat = 0; s = 1; p = u - 236; }
    else if (u < 440) { mat = 2; s = 1; p = u - 432; }
    else if (u < 636) { mat = 0; s = 2; p = u - 440; }
    else if (u < 644) { mat = 2; s = 2; p = u - 636; }
    else if (u < 840) { mat = 0; s = 3; p = u - 644; }
    else { mat = 2; s = 3; p = u - 840; }
}

// ---------------- kernel 1: repeated-softmax chain (P0 steps) ----------------
__global__ void g_chain_kernel(const float* __restrict__ g0) {
    int warp = threadIdx.x >> 5, lane = threadIdx.x & 31;
    int b = blockIdx.x * 8 + warp;
    float v[8];
#pragma unroll
    for (int r = 0; r < 8; r++) v[r] = g0[b * DD + r * 32 + lane];
    for (int p = 0; p < P0; p++) {
        float m = v[0];
#pragma unroll
        for (int r = 1; r < 8; r++) m = fmaxf(m, v[r]);
#pragma unroll
        for (int s = 16; s > 0; s >>= 1) m = fmaxf(m, __shfl_xor_sync(0xffffffffu, m, s));
        float s = 0.f;
#pragma unroll
        for (int r = 0; r < 8; r++) { v[r] = __expf(v[r] - m); s += v[r]; }
#pragma unroll
        for (int t = 16; t > 0; t >>= 1) s += __shfl_xor_sync(0xffffffffu, s, t);
        float inv = 1.f / s;
        float sq = 0.f;
#pragma unroll
        for (int r = 0; r < 8; r++) { v[r] *= inv; sq += v[r] * v[r]; }
#pragma unroll
        for (int t = 16; t > 0; t >>= 1) sq += __shfl_xor_sync(0xffffffffu, sq, t);
        float sc = 1.f / (sqrtf(sq) + 1e-8f);
        __nv_bfloat16* dst = &g_hat[((size_t)p * BB + b) * DD];
#pragma unroll
        for (int r = 0; r < 8; r++) dst[r * 32 + lane] = __float2bfloat16(v[r] * sc);
    }
}

// ---------------- kernel 2: tiled transpose + softmax + normalize + pos-dot ----
// grid (7, 512): block handles (28 p's, one b). 29.7KB smem -> 7 blocks/SM.
__global__ void __launch_bounds__(256) lf2_kernel(const float* __restrict__ outp) {
    __shared__ float fs[DD * LPITCH];
    int pt0 = blockIdx.x * PT, b = blockIdx.y;
    int tid = threadIdx.x, lane = tid & 31, warp = tid >> 5;
    const float* src = outp + (size_t)b * DD * PP + pt0;

    // gather: warp per row d (8 warps x 32 rows), explicit MLP-8 batches
    if (lane < PT) {
#pragma unroll
        for (int rr = 0; rr < 4; rr++) {
            float tmp[8];
#pragma unroll
            for (int k = 0; k < 8; k++)
                tmp[k] = src[(size_t)(warp + (rr * 8 + k) * 8) * PP + lane];
#pragma unroll
            for (int k = 0; k < 8; k++)
                fs[(warp + (rr * 8 + k) * 8) * LPITCH + lane] = tmp[k];
        }
    }
    __syncthreads();

    for (int pl = warp; pl < PT; pl += 8) {
        int p = pt0 + pl;
        float v[8];
#pragma unroll
        for (int r = 0; r < 8; r++) v[r] = fs[(r * 32 + lane) * LPITCH + pl];
        float m = v[0];
#pragma unroll
        for (int r = 1; r < 8; r++) m = fmaxf(m, v[r]);
#pragma unroll
        for (int s = 16; s > 0; s >>= 1) m = fmaxf(m, __shfl_xor_sync(0xffffffffu, m, s));
        float s = 0.f;
#pragma unroll
        for (int r = 0; r < 8; r++) { v[r] = __expf(v[r] - m); s += v[r]; }
#pragma unroll
        for (int t = 16; t > 0; t >>= 1) s += __shfl_xor_sync(0xffffffffu, s, t);
        float inv = 1.f / s;
        float sq = 0.f;
#pragma unroll
        for (int r = 0; r < 8; r++) { v[r] *= inv; sq += v[r] * v[r]; }
#pragma unroll
        for (int t = 16; t > 0; t >>= 1) sq += __shfl_xor_sync(0xffffffffu, sq, t);
        float sc = 1.f / (sqrtf(sq) + 1e-8f);
        __nv_bfloat16* dst = &lf_hat[((size_t)p * BB + b) * DD];
        float dot = 0.f;
        if (p < P0) {
            const __nv_bfloat16* gp = &g_hat[((size_t)p * BB + b) * DD];
#pragma unroll
            for (int r = 0; r < 8; r++) {
                float z = v[r] * sc;
                dst[r * 32 + lane] = __float2bfloat16(z);
                dot += z * __bfloat162float(gp[r * 32 + lane]);
            }
#pragma unroll
            for (int t = 16; t > 0; t >>= 1) dot += __shfl_xor_sync(0xffffffffu, dot, t);
        } else {
            float ssum = 0.f;
#pragma unroll
            for (int r = 0; r < 8; r++) {
                float z = v[r] * sc;
                dst[r * 32 + lane] = __float2bfloat16(z);
                ssum += z;
            }
#pragma unroll
            for (int t = 16; t > 0; t >>= 1) ssum += __shfl_xor_sync(0xffffffffu, ssum, t);
            dot = ssum * (1.f / 16.f);  // X_i . uniform-unit-G
        }
        if (lane == 0) d_pos[(size_t)p * BB + b] = 2.f * dot;
    }
}

// ---------------- kernel 3: attention sums (coalesced column-sum) --------------
__global__ void wsum_kernel(const float* __restrict__ att) {
    int tid = threadIdx.x;
    int r0 = blockIdx.x * 32;
    float acc = 0.f;
    if (tid < PP) {
#pragma unroll 4
        for (int r = 0; r < 32; r++) acc += att[(size_t)(r0 + r) * PP + tid];
        atomicAdd(&w_g[tid], acc);
    }
}

// ---------------- kernel 4: persistent mma.sync Gram GEMM, work-stealing -------
__global__ void __launch_bounds__(256, 1) gemm_kernel() {
    extern __shared__ __align__(16) __nv_bfloat16 smem[];
    __shared__ int u_sh;
    uint32_t sA_u = smem_u32(smem);
    uint32_t sB_u[2] = {sA_u + 128 * SPITCH * 2, sA_u + 2 * 128 * SPITCH * 2};

    int tid = threadIdx.x, lane = tid & 31, warp = tid >> 5;
    int warpM = warp & 1, warpN = warp >> 1;
    int g8 = lane & 7, q = lane >> 3;
    int g4 = lane >> 2, c2 = (lane & 3) * 2;

    while (true) {
        if (tid == 0) u_sh = (int)atomicAdd(&unit_ctr, 1u);
        __syncthreads();
        int u = u_sh;
        if (u >= NUNITS) break;

        int mat, p, s;
        unit_decode(u, mat, p, s);
        int cstart = (mat == 1) ? 0 : s;
        const __nv_bfloat16* L = (mat == 2) ? g_hat : lf_hat;
        const __nv_bfloat16* R = (mat == 0) ? lf_hat : g_hat;

        load_strip(sA_u, L + ((size_t)p * BB + s * 128) * DD, tid);
        load_strip(sB_u[0], R + ((size_t)p * BB + cstart * 128) * DD, tid);
        CP_COMMIT();

        float rowpart[8];
#pragma unroll
        for (int k = 0; k < 8; k++) rowpart[k] = 0.f;

        int nb = 0;
        for (int c = cstart; c < 4; c++) {
            if (c + 1 < 4) {
                load_strip(sB_u[nb ^ 1], R + ((size_t)p * BB + (c + 1) * 128) * DD, tid);
                CP_COMMIT();
                CP_WAIT1();
            } else {
                CP_WAIT0();
            }
            __syncthreads();

            float acc[4][4][4];
#pragma unroll
            for (int mt = 0; mt < 4; mt++)
#pragma unroll
                for (int nt = 0; nt < 4; nt++)
#pragma unroll
                    for (int e = 0; e < 4; e++) acc[mt][nt][e] = 0.f;

            uint32_t sBc = sB_u[nb];
            for (int kk = 0; kk < DD; kk += 16) {
                uint32_t a[4][4], bfr[4][2];
#pragma unroll
                for (int mt = 0; mt < 4; mt++) {
                    int ar = warpM * 64 + mt * 16 + g8 + ((q & 1) ? 8 : 0);
                    int ac = kk + ((q & 2) ? 8 : 0);
                    ldsm_x4(a[mt][0], a[mt][1], a[mt][2], a[mt][3],
                            sA_u + (uint32_t)(ar * SPITCH + ac) * 2u);
                }
#pragma unroll
                for (int pr = 0; pr < 2; pr++) {
                    int nbv = warpN * 32 + pr * 16 + ((q & 2) ? 8 : 0) + g8;
                    int bc = kk + ((q & 1) ? 8 : 0);
                    ldsm_x4(bfr[2 * pr][0], bfr[2 * pr][1], bfr[2 * pr + 1][0],
                            bfr[2 * pr + 1][1], sBc + (uint32_t)(nbv * SPITCH + bc) * 2u);
                }
#pragma unroll
                for (int mt = 0; mt < 4; mt++)
#pragma unroll
                    for (int nt = 0; nt < 4; nt++) mma16816(acc[mt][nt], a[mt], bfr[nt]);
            }

            bool excl = (mat != 1) && (c == s);
            bool docol = (mat == 1) || (c > s);
            float cp[8];
#pragma unroll
            for (int k = 0; k < 8; k++) cp[k] = 0.f;
#pragma unroll
            for (int mt = 0; mt < 4; mt++) {
                int row_lo = warpM * 64 + mt * 16 + g4;
#pragma unroll
                for (int nt = 0; nt < 4; nt++) {
                    int col = warpN * 32 + nt * 8 + c2;
                    float e0 = __expf(2.f * acc[mt][nt][0]);
                    float e1 = __expf(2.f * acc[mt][nt][1]);
                    float e2 = __expf(2.f * acc[mt][nt][2]);
                    float e3 = __expf(2.f * acc[mt][nt][3]);
                    if (excl) {
                        if (row_lo == col) e0 = 0.f;
                        if (row_lo == col + 1) e1 = 0.f;
                        if (row_lo + 8 == col) e2 = 0.f;
                        if (row_lo + 8 == col + 1) e3 = 0.f;
                    }
                    rowpart[2 * mt] += e0 + e1;
                    rowpart[2 * mt + 1] += e2 + e3;
                    if (docol) {
                        cp[2 * nt] += e0 + e2;
                        cp[2 * nt + 1] += e1 + e3;
                    }
                }
            }
            if (docol) {
#pragma unroll
                for (int k = 0; k < 8; k++) {
                    cp[k] += __shfl_xor_sync(0xffffffffu, cp[k], 4);
                    cp[k] += __shfl_xor_sync(0xffffffffu, cp[k], 8);
                    cp[k] += __shfl_xor_sync(0xffffffffu, cp[k], 16);
                }
                float* cdst = (mat == 1) ? colB_g : ((mat == 0) ? rowA_g : rowC_g);
                if (lane < 4) {
#pragma unroll
                    for (int nt = 0; nt < 4; nt++) {
                        int col = c * 128 + warpN * 32 + nt * 8 + lane * 2;
                        atomicAdd(&cdst[(size_t)p * BB + col], cp[2 * nt]);
                        atomicAdd(&cdst[(size_t)p * BB + col + 1], cp[2 * nt + 1]);
                    }
                }
            }
            __syncthreads();
            nb ^= 1;
        }

#pragma unroll
        for (int k = 0; k < 8; k++) {
            rowpart[k] += __shfl_xor_sync(0xffffffffu, rowpart[k], 1);
            rowpart[k] += __shfl_xor_sync(0xffffffffu, rowpart[k], 2);
        }
        float* rdst = (mat == 0) ? rowA_g : ((mat == 1) ? rowB_g : rowC_g);
        if ((lane & 3) == 0) {
#pragma unroll
            for (int mt = 0; mt < 4; mt++) {
                int row = s * 128 + warpM * 64 + mt * 16 + g4;
                atomicAdd(&rdst[(size_t)p * BB + row], rowpart[2 * mt]);
                atomicAdd(&rdst[(size_t)p * BB + row + 8], rowpart[2 * mt + 1]);
            }
        }
    }
}

// ---------------- kernel 5: per-position loss ----------------
__global__ void finalize1_kernel() {
    __shared__ float red[16];
    __shared__ float Tsh;
    int p = blockIdx.x, tid = threadIdx.x;
    int lane = tid & 31, warp = tid >> 5;
    size_t base = (size_t)p * BB + tid;
    float dp = d_pos[base];
    float rA = rowA_g[base];
    float stop, sbot;
    if (p < P0) {
        stop = rA + rowB_g[base];
        sbot = rowC_g[base] + colB_g[base];
    } else {
        float e = __expf(dp);
        float t = e;
#pragma unroll
        for (int s = 16; s > 0; s >>= 1) t += __shfl_xor_sync(0xffffffffu, t, s);
        if (lane == 0) red[warp] = t;
        __syncthreads();
        if (warp == 0) {
            t = red[lane & 15];
#pragma unroll
            for (int s = 8; s > 0; s >>= 1) t += __shfl_xor_sync(0xffffffffu, t, s);
            if (lane == 0) Tsh = t;
        }
        __syncthreads();
        stop = rA + 512.f * e;
        sbot = Tsh + 511.f * 7.3890560989306495f;  // 511*e^2
        __syncthreads();
    }
    float v = 2.f * dp - logf(stop) - logf(sbot);
#pragma unroll
    for (int s = 16; s > 0; s >>= 1) v += __shfl_xor_sync(0xffffffffu, v, s);
    if (lane == 0) red[warp] = v;
    __syncthreads();
    if (warp == 0) {
        v = red[lane & 15];
#pragma unroll
        for (int s = 8; s > 0; s >>= 1) v += __shfl_xor_sync(0xffffffffu, v, s);
        if (lane == 0)
            part_g[p] = -w_g[p] * (1.f / (512.f * 196.f)) * v * (1.f / 1024.f);
    }
}

// ---------------- kernel 6: final sum ----------------
__global__ void finalize2_kernel(float* __restrict__ out) {
    __shared__ float red[8];
    int tid = threadIdx.x;
    float v = (tid < PP) ? part_g[tid] : 0.f;
    int lane = tid & 31, warp = tid >> 5;
#pragma unroll
    for (int s = 16; s > 0; s >>= 1) v += __shfl_xor_sync(0xffffffffu, v, s);
    if (lane == 0) red[warp] = v;
    __syncthreads();
    if (warp == 0) {
        v = (lane < 8) ? red[lane] : 0.f;
#pragma unroll
        for (int s = 4; s > 0; s >>= 1) v += __shfl_xor_sync(0xffffffffu, v, s);
        if (lane == 0) out[0] = v;
    }
}

// ---------------- launch ----------------
extern "C" void kernel_launch(void* const* d_in, const int* in_sizes, int n_in,
                              void* d_out, int out_size) {
    const float* gf = (const float*)d_in[0];    // global_feature [512,256]
    const float* att = (const float*)d_in[1];   // att [512,8,14,14]
    const float* outp = (const float*)d_in[2];  // outputs [512,256,14,14]
    float* out = (float*)d_out;

    const int gemm_smem = 3 * 128 * SPITCH * 2;  // A + 2xB = 198 KB
    cudaFuncSetAttribute(gemm_kernel, cudaFuncAttributeMaxDynamicSharedMemorySize,
                         gemm_smem);

    void *pA, *pB, *pC, *pCol, *pW, *pCtr;
    cudaGetSymbolAddress(&pA, rowA_g);
    cudaGetSymbolAddress(&pB, rowB_g);
    cudaGetSymbolAddress(&pC, rowC_g);
    cudaGetSymbolAddress(&pCol, colB_g);
    cudaGetSymbolAddress(&pW, w_g);
    cudaGetSymbolAddress(&pCtr, unit_ctr);
    cudaMemsetAsync(pA, 0, (size_t)PP * BB * sizeof(float));
    cudaMemsetAsync(pB, 0, (size_t)P0 * BB * sizeof(float));
    cudaMemsetAsync(pC, 0, (size_t)P0 * BB * sizeof(float));
    cudaMemsetAsync(pCol, 0, (size_t)P0 * BB * sizeof(float));
    cudaMemsetAsync(pW, 0, PP * sizeof(float));
    cudaMemsetAsync(pCtr, 0, sizeof(unsigned int));

    g_chain_kernel<<<64, 256>>>(gf);
    lf2_kernel<<<dim3(7, BB), 256>>>(outp);
    wsum_kernel<<<128, 256>>>(att);  // 4096 rows = 128 blocks x 32 rows
    gemm_kernel<<<148, 256, gemm_smem>>>();
    finalize1_kernel<<<PP, 512>>>();
    finalize2_kernel<<<1, 256>>>(out);
}

// round 17
// speedup vs baseline: 2.4467x; 1.0171x over previous
#include <cuda_runtime.h>
#include <cuda_bf16.h>
#include <cstdint>

#define BB 512
#define DD 256
#define PP 196
#define P0 8          // positions computed exactly; p>=P0 uses analytic uniform-G path
#define SPITCH 264    // padded bf16 row pitch (528B) -> conflict-free ldmatrix
#define NUNITS 848    // 784 (A) + 32 (B, p<8) + 32 (C, p<8)
#define PT 28         // p-tile for lf prep (196 = 7*28)
#define LPITCH 29     // f32 smem pitch; 29 odd -> conflict-free strided reads

// ---------------- scratch (static device arrays; no allocation) ----------------
__device__ __nv_bfloat16 g_hat[(size_t)P0 * BB * DD];   // normalized softmax^p(g), p<P0
__device__ __nv_bfloat16 lf_hat[(size_t)PP * BB * DD];  // normalized softmax(local)
__device__ float d_pos[(size_t)PP * BB];                // sim of the positive pair
__device__ float rowA_g[(size_t)PP * BB];
__device__ float rowB_g[(size_t)P0 * BB];
__device__ float rowC_g[(size_t)P0 * BB];
__device__ float colB_g[(size_t)P0 * BB];
__device__ float w_g[PP];
__device__ float part_g[PP];
__device__ unsigned int unit_ctr;

// ---------------- helpers ----------------
__device__ __forceinline__ uint32_t smem_u32(const void* p) {
    return (uint32_t)__cvta_generic_to_shared(p);
}
__device__ __forceinline__ void ldsm_x4(uint32_t& r0, uint32_t& r1, uint32_t& r2,
                                        uint32_t& r3, uint32_t addr) {
    asm volatile("ldmatrix.sync.aligned.m8n8.x4.shared.b16 {%0,%1,%2,%3}, [%4];\n"
                 : "=r"(r0), "=r"(r1), "=r"(r2), "=r"(r3)
                 : "r"(addr));
}
__device__ __forceinline__ void mma16816(float* c, const uint32_t* a, const uint32_t* b) {
    asm volatile(
        "mma.sync.aligned.m16n8k16.row.col.f32.bf16.bf16.f32 "
        "{%0,%1,%2,%3}, {%4,%5,%6,%7}, {%8,%9}, {%0,%1,%2,%3};\n"
        : "+f"(c[0]), "+f"(c[1]), "+f"(c[2]), "+f"(c[3])
        : "r"(a[0]), "r"(a[1]), "r"(a[2]), "r"(a[3]), "r"(b[0]), "r"(b[1]));
}
__device__ __forceinline__ void cp16(uint32_t dst, const void* src) {
    asm volatile("cp.async.cg.shared.global [%0], [%1], 16;\n" ::"r"(dst), "l"(src));
}
#define CP_COMMIT() asm volatile("cp.async.commit_group;\n" ::: "memory")
#define CP_WAIT0() asm volatile("cp.async.wait_group 0;\n" ::: "memory")
#define CP_WAIT1() asm volatile("cp.async.wait_group 1;\n" ::: "memory")

__device__ __forceinline__ void load_strip(uint32_t sb, const __nv_bfloat16* src,
                                           int tid) {
    for (int i = tid; i < 128 * 32; i += 512) {
        int r = i >> 5, cs = i & 31;
        cp16(sb + (uint32_t)(r * SPITCH * 2 + cs * 16), src + (size_t)r * DD + cs * 8);
    }
}

// LPT order: cost-4 units first (A s=0, B, C s=0), then descending.
__device__ __forceinline__ void unit_decode(int u, int& mat, int& p, int& s) {
    if (u < 196) { mat = 0; s = 0; p = u; }
    else if (u < 204) { mat = 2; s = 0; p = u - 196; }
    else if (u < 236) { int v = u - 204; mat = 1; s = v & 3; p = v >> 2; }
    else if (u < 432) { mat = 0; s = 1; p = u - 236; }
    else if (u < 440) { mat = 2; s = 1; p = u - 432; }
    else if (u < 636) { mat = 0; s = 2; p = u - 440; }
    else if (u < 644) { mat = 2; s = 2; p = u - 636; }
    else if (u < 840) { mat = 0; s = 3; p = u - 644; }
    else { mat = 2; s = 3; p = u - 840; }
}

// ---------------- kernel 1: repeated-softmax chain (P0 steps) ----------------
__global__ void g_chain_kernel(const float* __restrict__ g0) {
    int warp = threadIdx.x >> 5, lane = threadIdx.x & 31;
    int b = blockIdx.x * 8 + warp;
    float v[8];
#pragma unroll
    for (int r = 0; r < 8; r++) v[r] = g0[b * DD + r * 32 + lane];
    for (int p = 0; p < P0; p++) {
        float m = v[0];
#pragma unroll
        for (int r = 1; r < 8; r++) m = fmaxf(m, v[r]);
#pragma unroll
        for (int s = 16; s > 0; s >>= 1) m = fmaxf(m, __shfl_xor_sync(0xffffffffu, m, s));
        float s = 0.f;
#pragma unroll
        for (int r = 0; r < 8; r++) { v[r] = __expf(v[r] - m); s += v[r]; }
#pragma unroll
        for (int t = 16; t > 0; t >>= 1) s += __shfl_xor_sync(0xffffffffu, s, t);
        float inv = 1.f / s;
        float sq = 0.f;
#pragma unroll
        for (int r = 0; r < 8; r++) { v[r] *= inv; sq += v[r] * v[r]; }
#pragma unroll
        for (int t = 16; t > 0; t >>= 1) sq += __shfl_xor_sync(0xffffffffu, sq, t);
        float sc = 1.f / (sqrtf(sq) + 1e-8f);
        __nv_bfloat16* dst = &g_hat[((size_t)p * BB + b) * DD];
#pragma unroll
        for (int r = 0; r < 8; r++) dst[r * 32 + lane] = __float2bfloat16(v[r] * sc);
    }
}

// ---------------- kernel 2: tiled transpose + softmax + normalize + pos-dot ----
// grid (7, 512): block handles (28 p's, one b). 29.7KB smem -> 7 blocks/SM.
__global__ void __launch_bounds__(256) lf2_kernel(const float* __restrict__ outp) {
    __shared__ float fs[DD * LPITCH];
    int pt0 = blockIdx.x * PT, b = blockIdx.y;
    int tid = threadIdx.x, lane = tid & 31, warp = tid >> 5;
    const float* src = outp + (size_t)b * DD * PP + pt0;

    // gather: warp per row d (8 warps x 32 rows), explicit MLP-8 batches
    if (lane < PT) {
#pragma unroll
        for (int rr = 0; rr < 4; rr++) {
            float tmp[8];
#pragma unroll
            for (int k = 0; k < 8; k++)
                tmp[k] = src[(size_t)(warp + (rr * 8 + k) * 8) * PP + lane];
#pragma unroll
            for (int k = 0; k < 8; k++)
                fs[(warp + (rr * 8 + k) * 8) * LPITCH + lane] = tmp[k];
        }
    }
    __syncthreads();

    for (int pl = warp; pl < PT; pl += 8) {
        int p = pt0 + pl;
        float v[8];
#pragma unroll
        for (int r = 0; r < 8; r++) v[r] = fs[(r * 32 + lane) * LPITCH + pl];
        float m = v[0];
#pragma unroll
        for (int r = 1; r < 8; r++) m = fmaxf(m, v[r]);
#pragma unroll
        for (int s = 16; s > 0; s >>= 1) m = fmaxf(m, __shfl_xor_sync(0xffffffffu, m, s));
        float s = 0.f;
#pragma unroll
        for (int r = 0; r < 8; r++) { v[r] = __expf(v[r] - m); s += v[r]; }
#pragma unroll
        for (int t = 16; t > 0; t >>= 1) s += __shfl_xor_sync(0xffffffffu, s, t);
        float inv = 1.f / s;
        float sq = 0.f;
#pragma unroll
        for (int r = 0; r < 8; r++) { v[r] *= inv; sq += v[r] * v[r]; }
#pragma unroll
        for (int t = 16; t > 0; t >>= 1) sq += __shfl_xor_sync(0xffffffffu, sq, t);
        float sc = 1.f / (sqrtf(sq) + 1e-8f);
        __nv_bfloat16* dst = &lf_hat[((size_t)p * BB + b) * DD];
        float dot = 0.f;
        if (p < P0) {
            const __nv_bfloat16* gp = &g_hat[((size_t)p * BB + b) * DD];
#pragma unroll
            for (int r = 0; r < 8; r++) {
                float z = v[r] * sc;
                dst[r * 32 + lane] = __float2bfloat16(z);
                dot += z * __bfloat162float(gp[r * 32 + lane]);
            }
#pragma unroll
            for (int t = 16; t > 0; t >>= 1) dot += __shfl_xor_sync(0xffffffffu, dot, t);
        } else {
            float ssum = 0.f;
#pragma unroll
            for (int r = 0; r < 8; r++) {
                float z = v[r] * sc;
                dst[r * 32 + lane] = __float2bfloat16(z);
                ssum += z;
            }
#pragma unroll
            for (int t = 16; t > 0; t >>= 1) ssum += __shfl_xor_sync(0xffffffffu, ssum, t);
            dot = ssum * (1.f / 16.f);  // X_i . uniform-unit-G
        }
        if (lane == 0) d_pos[(size_t)p * BB + b] = 2.f * dot;
    }
}

// ---------------- kernel 3: attention sums (coalesced column-sum) --------------
__global__ void wsum_kernel(const float* __restrict__ att) {
    int tid = threadIdx.x;
    int r0 = blockIdx.x * 32;
    float acc = 0.f;
    if (tid < PP) {
#pragma unroll 4
        for (int r = 0; r < 32; r++) acc += att[(size_t)(r0 + r) * PP + tid];
        atomicAdd(&w_g[tid], acc);
    }
}

// ---------------- kernel 4: persistent mma.sync Gram GEMM, work-stealing -------
// 512 threads / 16 warps (4x4 warp grid, 32x32 per warp): 4 warps per SMSP for
// latency hiding. Same 128x128 tile, B double-buffered, LPT work-stealing.
__global__ void __launch_bounds__(512, 1) gemm_kernel() {
    extern __shared__ __align__(16) __nv_bfloat16 smem[];
    __shared__ int u_sh;
    uint32_t sA_u = smem_u32(smem);
    uint32_t sB_u[2] = {sA_u + 128 * SPITCH * 2, sA_u + 2 * 128 * SPITCH * 2};

    int tid = threadIdx.x, lane = tid & 31, warp = tid >> 5;
    int warpM = warp & 3, warpN = warp >> 2;
    int g8 = lane & 7, q = lane >> 3;
    int g4 = lane >> 2, c2 = (lane & 3) * 2;

    while (true) {
        if (tid == 0) u_sh = (int)atomicAdd(&unit_ctr, 1u);
        __syncthreads();
        int u = u_sh;
        if (u >= NUNITS) break;

        int mat, p, s;
        unit_decode(u, mat, p, s);
        int cstart = (mat == 1) ? 0 : s;
        const __nv_bfloat16* L = (mat == 2) ? g_hat : lf_hat;
        const __nv_bfloat16* R = (mat == 0) ? lf_hat : g_hat;

        load_strip(sA_u, L + ((size_t)p * BB + s * 128) * DD, tid);
        load_strip(sB_u[0], R + ((size_t)p * BB + cstart * 128) * DD, tid);
        CP_COMMIT();

        float rowpart[4];
#pragma unroll
        for (int k = 0; k < 4; k++) rowpart[k] = 0.f;

        int nb = 0;
        for (int c = cstart; c < 4; c++) {
            if (c + 1 < 4) {
                load_strip(sB_u[nb ^ 1], R + ((size_t)p * BB + (c + 1) * 128) * DD, tid);
                CP_COMMIT();
                CP_WAIT1();
            } else {
                CP_WAIT0();
            }
            __syncthreads();

            float acc[2][4][4];
#pragma unroll
            for (int mt = 0; mt < 2; mt++)
#pragma unroll
                for (int nt = 0; nt < 4; nt++)
#pragma unroll
                    for (int e = 0; e < 4; e++) acc[mt][nt][e] = 0.f;

            uint32_t sBc = sB_u[nb];
            for (int kk = 0; kk < DD; kk += 16) {
                uint32_t a[2][4], bfr[4][2];
#pragma unroll
                for (int mt = 0; mt < 2; mt++) {
                    int ar = warpM * 32 + mt * 16 + g8 + ((q & 1) ? 8 : 0);
                    int ac = kk + ((q & 2) ? 8 : 0);
                    ldsm_x4(a[mt][0], a[mt][1], a[mt][2], a[mt][3],
                            sA_u + (uint32_t)(ar * SPITCH + ac) * 2u);
                }
#pragma unroll
                for (int pr = 0; pr < 2; pr++) {
                    int nbv = warpN * 32 + pr * 16 + ((q & 2) ? 8 : 0) + g8;
                    int bc = kk + ((q & 1) ? 8 : 0);
                    ldsm_x4(bfr[2 * pr][0], bfr[2 * pr][1], bfr[2 * pr + 1][0],
                            bfr[2 * pr + 1][1], sBc + (uint32_t)(nbv * SPITCH + bc) * 2u);
                }
#pragma unroll
                for (int mt = 0; mt < 2; mt++)
#pragma unroll
                    for (int nt = 0; nt < 4; nt++) mma16816(acc[mt][nt], a[mt], bfr[nt]);
            }

            bool excl = (mat != 1) && (c == s);
            bool docol = (mat == 1) || (c > s);
            float cp[8];
#pragma unroll
            for (int k = 0; k < 8; k++) cp[k] = 0.f;
#pragma unroll
            for (int mt = 0; mt < 2; mt++) {
                int row_lo = warpM * 32 + mt * 16 + g4;
#pragma unroll
                for (int nt = 0; nt < 4; nt++) {
                    int col = warpN * 32 + nt * 8 + c2;
                    float e0 = __expf(2.f * acc[mt][nt][0]);
                    float e1 = __expf(2.f * acc[mt][nt][1]);
                    float e2 = __expf(2.f * acc[mt][nt][2]);
                    float e3 = __expf(2.f * acc[mt][nt][3]);
                    if (excl) {
                        if (row_lo == col) e0 = 0.f;
                        if (row_lo == col + 1) e1 = 0.f;
                        if (row_lo + 8 == col) e2 = 0.f;
                        if (row_lo + 8 == col + 1) e3 = 0.f;
                    }
                    rowpart[2 * mt] += e0 + e1;
                    rowpart[2 * mt + 1] += e2 + e3;
                    if (docol) {
                        cp[2 * nt] += e0 + e2;
                        cp[2 * nt + 1] += e1 + e3;
                    }
                }
            }
            if (docol) {
#pragma unroll
                for (int k = 0; k < 8; k++) {
                    cp[k] += __shfl_xor_sync(0xffffffffu, cp[k], 4);
                    cp[k] += __shfl_xor_sync(0xffffffffu, cp[k], 8);
                    cp[k] += __shfl_xor_sync(0xffffffffu, cp[k], 16);
                }
                float* cdst = (mat == 1) ? colB_g : ((mat == 0) ? rowA_g : rowC_g);
                if (lane < 4) {
#pragma unroll
                    for (int nt = 0; nt < 4; nt++) {
                        int col = c * 128 + warpN * 32 + nt * 8 + lane * 2;
                        atomicAdd(&cdst[(size_t)p * BB + col], cp[2 * nt]);
                        atomicAdd(&cdst[(size_t)p * BB + col + 1], cp[2 * nt + 1]);
                    }
                }
            }
            __syncthreads();
            nb ^= 1;
        }

#pragma unroll
        for (int k = 0; k < 4; k++) {
            rowpart[k] += __shfl_xor_sync(0xffffffffu, rowpart[k], 1);
            rowpart[k] += __shfl_xor_sync(0xffffffffu, rowpart[k], 2);
        }
        float* rdst = (mat == 0) ? rowA_g : ((mat == 1) ? rowB_g : rowC_g);
        if ((lane & 3) == 0) {
#pragma unroll
            for (int mt = 0; mt < 2; mt++) {
                int row = s * 128 + warpM * 32 + mt * 16 + g4;
                atomicAdd(&rdst[(size_t)p * BB + row], rowpart[2 * mt]);
                atomicAdd(&rdst[(size_t)p * BB + row + 8], rowpart[2 * mt + 1]);
            }
        }
    }
}

// ---------------- kernel 5: per-position loss ----------------
__global__ void finalize1_kernel() {
    __shared__ float red[16];
    __shared__ float Tsh;
    int p = blockIdx.x, tid = threadIdx.x;
    int lane = tid & 31, warp = tid >> 5;
    size_t base = (size_t)p * BB + tid;
    float dp = d_pos[base];
    float rA = rowA_g[base];
    float stop, sbot;
    if (p < P0) {
        stop = rA + rowB_g[base];
        sbot = rowC_g[base] + colB_g[base];
    } else {
        float e = __expf(dp);
        float t = e;
#pragma unroll
        for (int s = 16; s > 0; s >>= 1) t += __shfl_xor_sync(0xffffffffu, t, s);
        if (lane == 0) red[warp] = t;
        __syncthreads();
        if (warp == 0) {
            t = red[lane & 15];
#pragma unroll
            for (int s = 8; s > 0; s >>= 1) t += __shfl_xor_sync(0xffffffffu, t, s);
            if (lane == 0) Tsh = t;
        }
        __syncthreads();
        stop = rA + 512.f * e;
        sbot = Tsh + 511.f * 7.3890560989306495f;  // 511*e^2
        __syncthreads();
    }
    float v = 2.f * dp - logf(stop) - logf(sbot);
#pragma unroll
    for (int s = 16; s > 0; s >>= 1) v += __shfl_xor_sync(0xffffffffu, v, s);
    if (lane == 0) red[warp] = v;
    __syncthreads();
    if (warp == 0) {
        v = red[lane & 15];
#pragma unroll
        for (int s = 8; s > 0; s >>= 1) v += __shfl_xor_sync(0xffffffffu, v, s);
        if (lane == 0)
            part_g[p] = -w_g[p] * (1.f / (512.f * 196.f)) * v * (1.f / 1024.f);
    }
}

// ---------------- kernel 6: final sum ----------------
__global__ void finalize2_kernel(float* __restrict__ out) {
    __shared__ float red[8];
    int tid = threadIdx.x;
    float v = (tid < PP) ? part_g[tid] : 0.f;
    int lane = tid & 31, warp = tid >> 5;
#pragma unroll
    for (int s = 16; s > 0; s >>= 1) v += __shfl_xor_sync(0xffffffffu, v, s);
    if (lane == 0) red[warp] = v;
    __syncthreads();
    if (warp == 0) {
        v = (lane < 8) ? red[lane] : 0.f;
#pragma unroll
        for (int s = 4; s > 0; s >>= 1) v += __shfl_xor_sync(0xffffffffu, v, s);
        if (lane == 0) out[0] = v;
    }
}

// ---------------- launch ----------------
extern "C" void kernel_launch(void* const* d_in, const int* in_sizes, int n_in,
                              void* d_out, int out_size) {
    const float* gf = (const float*)d_in[0];    // global_feature [512,256]
    const float* att = (const float*)d_in[1];   // att [512,8,14,14]
    const float* outp = (const float*)d_in[2];  // outputs [512,256,14,14]
    float* out = (float*)d_out;

    const int gemm_smem = 3 * 128 * SPITCH * 2;  // A + 2xB = 198 KB
    cudaFuncSetAttribute(gemm_kernel, cudaFuncAttributeMaxDynamicSharedMemorySize,
                         gemm_smem);

    void *pA, *pB, *pC, *pCol, *pW, *pCtr;
    cudaGetSymbolAddress(&pA, rowA_g);
    cudaGetSymbolAddress(&pB, rowB_g);
    cudaGetSymbolAddress(&pC, rowC_g);
    cudaGetSymbolAddress(&pCol, colB_g);
    cudaGetSymbolAddress(&pW, w_g);
    cudaGetSymbolAddress(&pCtr, unit_ctr);
    cudaMemsetAsync(pA, 0, (size_t)PP * BB * sizeof(float));
    cudaMemsetAsync(pB, 0, (size_t)P0 * BB * sizeof(float));
    cudaMemsetAsync(pC, 0, (size_t)P0 * BB * sizeof(float));
    cudaMemsetAsync(pCol, 0, (size_t)P0 * BB * sizeof(float));
    cudaMemsetAsync(pW, 0, PP * sizeof(float));
    cudaMemsetAsync(pCtr, 0, sizeof(unsigned int));

    g_chain_kernel<<<64, 256>>>(gf);
    lf2_kernel<<<dim3(7, BB), 256>>>(outp);
    wsum_kernel<<<128, 256>>>(att);  // 4096 rows = 128 blocks x 32 rows
    gemm_kernel<<<148, 512, gemm_smem>>>();
    finalize1_kernel<<<PP, 512>>>();
    finalize2_kernel<<<1, 256>>>(out);
}